// round 3
// baseline (speedup 1.0000x reference)
#include <cuda_runtime.h>
#include <cstdint>

#define BATCH 512
#define N 256
constexpr float FINF = 1e30f;

// Scratch: transposed + sanitized + pad-zeroed cost matrices (128 MiB, static — no runtime alloc).
__device__ float g_P[(size_t)BATCH * N * N];
__device__ int   g_nk[BATCH];

// ---------------------------------------------------------------------------
// Kernel 1: n_k[b] = count of nonzero mask words. Mask read as 32-bit words:
// correct for bool widened to int32 (0/1) OR float32 (0.0f/1.0f).
// ---------------------------------------------------------------------------
__global__ void nk_kernel(const unsigned int* __restrict__ mask) {
    int b = blockIdx.x;
    int t = threadIdx.x;  // 256 threads
    int v = (mask[b * N + t] != 0u) ? 1 : 0;
#pragma unroll
    for (int off = 16; off; off >>= 1) v += __shfl_xor_sync(0xffffffffu, v, off);
    __shared__ int s[8];
    if ((t & 31) == 0) s[t >> 5] = v;
    __syncthreads();
    if (t == 0) {
        int tot = 0;
#pragma unroll
        for (int w = 0; w < 8; w++) tot += s[w];
        g_nk[b] = tot;
    }
}

// ---------------------------------------------------------------------------
// Kernel 2: P[b][i][j] = sanitize(costs[b][j][i]) for i < n_k[b], else 0
// (nan/±inf -> 1e6, replicating jnp.nan_to_num with those fills)
// ---------------------------------------------------------------------------
__global__ void transpose_kernel(const float* __restrict__ costs) {
    __shared__ float tile[32][33];
    int b  = blockIdx.z;
    int i0 = blockIdx.x * 32;   // output row block (object index i)
    int j0 = blockIdx.y * 32;   // output col block (prediction index j)
    int tx = threadIdx.x, ty = threadIdx.y;  // 32 x 8
    const float* src = costs + (size_t)b * N * N;
    float*       dst = g_P   + (size_t)b * N * N;
#pragma unroll
    for (int s = 0; s < 32; s += 8) {
        float x = src[(size_t)(j0 + ty + s) * N + (i0 + tx)];
        unsigned bits = __float_as_uint(x);
        if ((bits & 0x7f800000u) == 0x7f800000u) x = 1e6f;  // nan or +-inf
        tile[ty + s][tx] = x;
    }
    __syncthreads();
    int nkb = g_nk[b];
#pragma unroll
    for (int s = 0; s < 32; s += 8) {
        int i = i0 + ty + s;
        dst[(size_t)i * N + (j0 + tx)] = (i < nkb) ? tile[tx][ty + s] : 0.0f;
    }
}

// ---------------------------------------------------------------------------
// Kernel 3: one warp per batch, Jonker-Volgenant shortest augmenting path.
// Lane l owns columns j = l + 32*t (t = 0..7): shortest/pathrow/v/SC in regs.
// u, col4row, row4col + per-augment dumps in shared memory.
// Float op order and tie-breaking replicate the JAX reference exactly.
// Output written as FLOAT32 (harness materializes int indices as f32).
// ---------------------------------------------------------------------------
__global__ void __launch_bounds__(32) solve_kernel(float* __restrict__ out) {
    const int b    = blockIdx.x;
    const int lane = threadIdx.x;
    const float* P = g_P + (size_t)b * N * N;
    const int nk   = g_nk[b];

    __shared__ float u[N];
    __shared__ int   c4r[N];   // col4row
    __shared__ int   r4c[N];   // row4col
    __shared__ float shS[N];   // shortest dump (for u-dual gather)
    __shared__ int   shP[N];   // pathrow dump (for augmentation)

    float v[8];
#pragma unroll
    for (int t = 0; t < 8; t++) {
        int idx = lane + 32 * t;
        u[idx]   = 0.0f;
        c4r[idx] = -1;
        r4c[idx] = -1;
        v[t]     = 0.0f;
    }
    __syncwarp();

    for (int cur = 0; cur < N; ++cur) {
        float shortest[8];
        int   prow[8];
#pragma unroll
        for (int t = 0; t < 8; t++) { shortest[t] = FINF; prow[t] = -1; }
        unsigned scMask = 0, srMask = 0;
        int   i      = cur;
        float minval = 0.0f;
        int   sink   = -1;

        while (sink < 0) {
            if ((i & 31) == lane) srMask |= 1u << (i >> 5);   // SR[i] = true
            float ui = u[i];
            const float* Prow = P + (size_t)i * N;
            float cj[8];
#pragma unroll
            for (int t = 0; t < 8; t++) cj[t] = Prow[lane + 32 * t];  // 8 parallel LDGs

            float bestVal = FINF;
            int   bestJ   = 0x7fffffff;
#pragma unroll
            for (int t = 0; t < 8; t++) {
                float s;
                if (!((scMask >> t) & 1u)) {
                    // exact op order of reference: ((minval + cost) - u[i]) - v[j]
                    float r = ((minval + cj[t]) - ui) - v[t];
                    if (r < shortest[t]) { shortest[t] = r; prow[t] = i; }
                    s = shortest[t];
                } else {
                    s = FINF;  // masked
                }
                if (s < bestVal) { bestVal = s; bestJ = lane + 32 * t; }  // strict <: first j wins
            }
            // warp argmin, lexicographic (value, j) with float compares (+-0 tie -> smaller j,
            // matching jnp.argmin first-occurrence semantics)
#pragma unroll
            for (int off = 16; off; off >>= 1) {
                float ov = __shfl_xor_sync(0xffffffffu, bestVal, off);
                int   oj = __shfl_xor_sync(0xffffffffu, bestJ, off);
                if (ov < bestVal || (ov == bestVal && oj < bestJ)) { bestVal = ov; bestJ = oj; }
            }
            minval = bestVal;
            int jmin = bestJ;
            if ((jmin & 31) == lane) scMask |= 1u << (jmin >> 5);  // SC[jmin] = true
            int nxt = r4c[jmin];
            if (nxt < 0) sink = jmin;
            else         i   = nxt;
        }

        // dump per-column state for the gather + augmentation
#pragma unroll
        for (int t = 0; t < 8; t++) {
            int j = lane + 32 * t;
            shS[j] = shortest[t];
            shP[j] = prow[t];
        }
        __syncwarp();

        // dual updates (Crouse 2016 / scipy lsap), same op order as reference
#pragma unroll
        for (int t = 0; t < 8; t++) {
            int row = lane + 32 * t;
            if (row == cur) {
                u[row] = u[row] + minval;
            } else if ((srMask >> t) & 1u) {
                int c  = c4r[row];                 // assigned (>= 0) for SR rows != cur
                u[row] = u[row] + (minval - shS[c]);
            }
            if ((scMask >> t) & 1u) v[t] = v[t] - (minval - shortest[t]);
        }
        __syncwarp();

        // augment along alternating path back to cur (sequential, lane 0)
        if (lane == 0) {
            int j = sink;
            while (true) {
                int ii  = shP[j];
                r4c[j]  = ii;
                int jn  = c4r[ii];
                c4r[ii] = j;
                j = jn;
                if (ii == cur) break;
            }
        }
        __syncwarp();
    }

    // Output (as float32): valid rows take their assigned column; padded rows
    // take the unused prediction indices in ascending order (argsort fill).
    if (lane == 0) {
        float* ob = out + b * N;
        int    cnt = 0;
        for (int j = 0; j < N; j++)
            if (r4c[j] >= nk) ob[nk + cnt++] = (float)j;  // unused cols, ascending
        for (int i2 = 0; i2 < nk; i2++) ob[i2] = (float)c4r[i2];
    }
}

// ---------------------------------------------------------------------------
extern "C" void kernel_launch(void* const* d_in, const int* in_sizes, int n_in,
                              void* d_out, int out_size) {
    // Select inputs by element count, not position: costs = B*N*N, mask = B*N.
    int ci = 0, mi = 1;
    if (n_in >= 2 && in_sizes[0] == BATCH * N && in_sizes[1] == BATCH * N * N) {
        ci = 1; mi = 0;
    }
    const float*        costs = (const float*)d_in[ci];
    const unsigned int* mask  = (const unsigned int*)d_in[mi];  // int32 or fp32 0/1
    float* out = (float*)d_out;

    nk_kernel<<<BATCH, 256>>>(mask);
    transpose_kernel<<<dim3(N / 32, N / 32, BATCH), dim3(32, 8)>>>(costs);
    solve_kernel<<<BATCH, 32>>>(out);
}